// round 4
// baseline (speedup 1.0000x reference)
#include <cuda_runtime.h>
#include <cstdint>

#define KC 512
#define DD 64
#define NB 32
#define HW 4096
#define NVEC (NB * HW)              // 131072 vectors
#define NTH 256
#define NPT 2                       // vectors per thread
#define CHUNKN (NTH * NPT)          // 512 vectors per chunk
#define NCHUNK (NVEC / CHUNKN)      // 256 chunks
#define GRID 128
#define SMEM_BYTES (KC * DD * 4 + KC * 8)   // cb 131072B + cbsqr2 4096B

typedef unsigned long long u64;

// Packed fp32x2 ops (sm_100+; ptxas never auto-emits these from C++).
__device__ __forceinline__ u64 ffma2(u64 a, u64 b, u64 c) {
    u64 d;
    asm("fma.rn.f32x2 %0, %1, %2, %3;" : "=l"(d) : "l"(a), "l"(b), "l"(c));
    return d;
}
__device__ __forceinline__ u64 fadd2(u64 a, u64 b) {
    u64 d;
    asm("add.rn.f32x2 %0, %1, %2;" : "=l"(d) : "l"(a), "l"(b));
    return d;
}
__device__ __forceinline__ u64 pk(float lo, float hi) {
    u64 d;
    asm("mov.b64 %0, {%1, %2};" : "=l"(d) : "f"(lo), "f"(hi));
    return d;
}
__device__ __forceinline__ void unpack2(u64 a, float& lo, float& hi) {
    asm("mov.b64 {%0, %1}, %2;" : "=f"(lo), "=f"(hi) : "l"(a));
}

// Bit-exact fold of ((f0+f1)+(f2+f3)) + ((f4+f5)+(f6+f7)):
// every packed lane performs the identical two-operand add of the scalar tree.
__device__ __forceinline__ float tree8(u64 a0, u64 a1, u64 a2, u64 a3) {
    float f0, f1, f2, f3, f4, f5, f6, f7;
    unpack2(a0, f0, f1); unpack2(a1, f2, f3);
    unpack2(a2, f4, f5); unpack2(a3, f6, f7);
    u64 r01 = fadd2(pk(f0, f2), pk(f1, f3));   // {f0+f1, f2+f3}
    u64 r23 = fadd2(pk(f4, f6), pk(f5, f7));   // {f4+f5, f6+f7}
    float g0, g1, g2, g3;
    unpack2(r01, g0, g1); unpack2(r23, g2, g3);
    u64 v = fadd2(pk(g0, g2), pk(g1, g3));     // {g0+g1, g2+g3}
    float h0, h1;
    unpack2(v, h0, h1);
    return h0 + h1;
}

#define NEG2PK 0xC0000000C0000000ull   // {-2.0f, -2.0f}

__global__ void __launch_bounds__(NTH, 1)
vq_kernel(const float* __restrict__ ze, const float* __restrict__ cbg,
          float* __restrict__ out, int write2) {
    extern __shared__ float sm[];
    float* cb      = sm;                       // [512][64]
    u64*   cbsqr2  = (u64*)(sm + KC * DD);     // [512] duplicated {ck,ck}
    const int tid = threadIdx.x;

    {
        const float4* g4 = (const float4*)cbg;
        float4*       s4 = (float4*)cb;
        #pragma unroll
        for (int i = tid; i < KC * DD / 4; i += NTH) s4[i] = g4[i];
    }
    __syncthreads();
    for (int k = tid; k < KC; k += NTH) {
        const float* row = cb + k * DD;
        float s = 0.f;
        #pragma unroll
        for (int d = 0; d < DD; d++) s = fmaf(row[d], row[d], s);
        cbsqr2[k] = pk(s, s);
    }
    __syncthreads();

    const u64* cbq = (const u64*)cb;  // f32x2 pairs, 32 per row

    for (int chunk = blockIdx.x; chunk < NCHUNK; chunk += gridDim.x) {
        const int n0 = chunk * CHUNKN + tid;
        const int b  = n0 >> 12;
        const int s0 = n0 & 4095;
        const float* xa = ze + (size_t)b * (DD * HW) + s0;
        const float* xb = xa + NTH;             // s0 + 256, same b

        u64 x2a[DD / 2], x2b[DD / 2];
        float xsqra = 0.f, xsqrb = 0.f;
        #pragma unroll
        for (int j = 0; j < DD / 2; j++) {
            float la = xa[(size_t)(2 * j) * HW];
            float ha = xa[(size_t)(2 * j + 1) * HW];
            xsqra = fmaf(la, la, xsqra);
            xsqra = fmaf(ha, ha, xsqra);
            x2a[j] = pk(la, ha);
            float lb = xb[(size_t)(2 * j) * HW];
            float hb = xb[(size_t)(2 * j + 1) * HW];
            xsqrb = fmaf(lb, lb, xsqrb);
            xsqrb = fmaf(hb, hb, xsqrb);
            x2b[j] = pk(lb, hb);
        }
        const u64 xs2 = pk(xsqra, xsqrb);      // lane = vector

        float besta = 3.4028235e38f, bestb = 3.4028235e38f;
        int   bka = 0, bkb = 0;

        // Half-row double buffer (prefetch covers the 29-cyc LDS latency).
        u64 h0[16], h1[16];
        #pragma unroll
        for (int p = 0; p < 16; p++) h0[p] = cbq[p];   // k=0 first half

        #pragma unroll 4
        for (int k = 0; k < KC; k++) {
            const u64* cr = cbq + k * 32;

            #pragma unroll
            for (int p = 0; p < 16; p++) h1[p] = cr[16 + p];

            u64 a0 = 0ull, a1 = 0ull, a2 = 0ull, a3 = 0ull;
            u64 b0 = 0ull, b1 = 0ull, b2 = 0ull, b3 = 0ull;
            #pragma unroll
            for (int j = 0; j < 4; j++) {
                u64 c0 = h0[4 * j + 0], c1 = h0[4 * j + 1];
                u64 c2 = h0[4 * j + 2], c3 = h0[4 * j + 3];
                a0 = ffma2(x2a[4 * j + 0], c0, a0);
                b0 = ffma2(x2b[4 * j + 0], c0, b0);
                a1 = ffma2(x2a[4 * j + 1], c1, a1);
                b1 = ffma2(x2b[4 * j + 1], c1, b1);
                a2 = ffma2(x2a[4 * j + 2], c2, a2);
                b2 = ffma2(x2b[4 * j + 2], c2, b2);
                a3 = ffma2(x2a[4 * j + 3], c3, a3);
                b3 = ffma2(x2b[4 * j + 3], c3, b3);
            }
            // Prefetch first half of row k+1 (k=511 harmlessly reads cbsqr2).
            #pragma unroll
            for (int p = 0; p < 16; p++) h0[p] = cr[32 + p];
            #pragma unroll
            for (int j = 4; j < 8; j++) {
                u64 c0 = h1[4 * (j - 4) + 0], c1 = h1[4 * (j - 4) + 1];
                u64 c2 = h1[4 * (j - 4) + 2], c3 = h1[4 * (j - 4) + 3];
                a0 = ffma2(x2a[4 * j + 0], c0, a0);
                b0 = ffma2(x2b[4 * j + 0], c0, b0);
                a1 = ffma2(x2a[4 * j + 1], c1, a1);
                b1 = ffma2(x2b[4 * j + 1], c1, b1);
                a2 = ffma2(x2a[4 * j + 2], c2, a2);
                b2 = ffma2(x2b[4 * j + 2], c2, b2);
                a3 = ffma2(x2a[4 * j + 3], c3, a3);
                b3 = ffma2(x2b[4 * j + 3], c3, b3);
            }

            float dota = tree8(a0, a1, a2, a3);
            float dotb = tree8(b0, b1, b2, b3);
            // base.lane = ck + xsqr_lane ; dist.lane = fma(-2, dot_lane, base.lane)
            // — identical single roundings to the scalar forms.
            u64 base2 = fadd2(cbsqr2[k], xs2);
            u64 dist2 = ffma2(NEG2PK, pk(dota, dotb), base2);
            float da, db;
            unpack2(dist2, da, db);
            if (da < besta) { besta = da; bka = k; }
            if (db < bestb) { bestb = db; bkb = k; }
        }

        #pragma unroll
        for (int v = 0; v < NPT; v++) {
            const int   kk = (v == 0) ? bka : bkb;
            const int   ss = s0 + v * NTH;
            const float4* code4 = (const float4*)(cb + kk * DD);
            float* o1 = out + (size_t)b * (DD * HW) + ss;
            float* o2 = o1 + (size_t)NVEC * DD;
            #pragma unroll
            for (int q = 0; q < DD / 4; q++) {
                float4 w = code4[q];
                o1[(size_t)(4 * q + 0) * HW] = w.x;
                o1[(size_t)(4 * q + 1) * HW] = w.y;
                o1[(size_t)(4 * q + 2) * HW] = w.z;
                o1[(size_t)(4 * q + 3) * HW] = w.w;
                if (write2) {
                    o2[(size_t)(4 * q + 0) * HW] = w.x;
                    o2[(size_t)(4 * q + 1) * HW] = w.y;
                    o2[(size_t)(4 * q + 2) * HW] = w.z;
                    o2[(size_t)(4 * q + 3) * HW] = w.w;
                }
            }
        }
    }
}

extern "C" void kernel_launch(void* const* d_in, const int* in_sizes, int n_in,
                              void* d_out, int out_size) {
    const float* ze  = (const float*)d_in[0];   // z_e_x [32,64,64,64] f32
    const float* cbg = (const float*)d_in[1];   // codebook [512,64] f32
    float* out = (float*)d_out;
    const int write2 = (out_size >= 2 * NVEC * DD) ? 1 : 0;
    cudaFuncSetAttribute(vq_kernel, cudaFuncAttributeMaxDynamicSharedMemorySize,
                         (int)SMEM_BYTES);
    vq_kernel<<<GRID, NTH, SMEM_BYTES>>>(ze, cbg, out, write2);
}